// round 3
// baseline (speedup 1.0000x reference)
#include <cuda_runtime.h>
#include <math.h>

#define Bn 256
#define Sn 256
#define Tn 32
#define Hn 512
#define En 128
#define EDn 32
#define An 8
#define NTn 80

// Persistent scratch (no allocations allowed)
__device__ float g_h[2][Bn*Hn];          // double-buffered hidden state
__device__ float g_c[Bn*Hn];             // cell state
__device__ float g_enc_out[Sn*Bn*Hn];    // (S,B,H) encoder outputs, 134 MB
__device__ float g_enc_score[Sn*Bn];     // (S,B) attention logits (enc part)
__device__ int   g_inp[Bn*2];            // decoder feedback tokens

__device__ __forceinline__ float sigmoidf_(float x){ return 1.f/(1.f+expf(-x)); }

__global__ void init_k(){
    int i = blockIdx.x*blockDim.x + threadIdx.x;
    if (i < Bn*Hn){ g_h[0][i]=0.f; g_h[1][i]=0.f; g_c[i]=0.f; }
    if (i < Bn*2) g_inp[i]=0;
}

// ---------------------------------------------------------------------------
// Fused LSTM step: z = [x_t, h] @ W^T + b ; gates ; c,h update.
// Block computes a 32(batch) x 32(h-units) tile = 32x128 gate values, K = K1+H.
// Grid: 8 (batch tiles) x 16 (h tiles) = 128 blocks, 256 threads.
// ---------------------------------------------------------------------------
template<int K1, bool ENC>
__global__ __launch_bounds__(256) void lstm_k(
    const float* __restrict__ Wi, const float* __restrict__ Wh,
    const float* __restrict__ bias,
    const int*   __restrict__ enc_input, const float* __restrict__ enc_embed,
    const float* __restrict__ act_emb,   const float* __restrict__ tgt_emb,
    int t, int par)
{
    constexpr int KT  = K1 + Hn;
    constexpr int NKT = KT/16;
    __shared__ float As[16][34];     // [kk][row], padded
    __shared__ float Bs[16][136];    // [kk][col], padded (col = g*32+j local)
    __shared__ float zs[32*128];

    const int tid = threadIdx.x;
    const int b0  = (blockIdx.x & 7)  * 32;
    const int h0  = (blockIdx.x >> 3) * 32;
    const float* h_in  = g_h[par];
    float*       h_out = g_h[par^1];

    const int tr = tid >> 4;   // 0..15 -> rows 2tr,2tr+1
    const int cg = tid & 15;   // 0..15 -> cols cg*8..cg*8+7

    float acc[2][8];
    #pragma unroll
    for (int i=0;i<2;i++)
        #pragma unroll
        for (int j=0;j<8;j++) acc[i][j]=0.f;

    auto loadB4 = [&](int e4, int k0)->float4 {
        int crow = e4 >> 2;
        int k    = k0 + (e4 & 3)*4;
        int g = crow >> 5, j = crow & 31;
        int wrow = g*Hn + h0 + j;
        if (k < K1) return *(const float4*)(Wi + wrow*K1 + k);
        return *(const float4*)(Wh + wrow*Hn + (k - K1));
    };
    auto loadA4 = [&](int k0)->float4 {
        int r  = tid >> 2;
        int k  = k0 + (tid & 3)*4;
        int bg = b0 + r;
        if (k < K1){
            if (ENC){
                int vid = enc_input[bg*Sn + t];
                return *(const float4*)(enc_embed + vid*En + k);
            } else {
                if (k < EDn){
                    int a = g_inp[bg*2];
                    return *(const float4*)(act_emb + a*EDn + k);
                } else {
                    int tt = g_inp[bg*2+1];
                    return *(const float4*)(tgt_emb + tt*EDn + (k-EDn));
                }
            }
        }
        return *(const float4*)(h_in + bg*Hn + (k - K1));
    };

    // prefetch tile 0
    float4 bp0 = loadB4(tid, 0), bp1 = loadB4(tid+256, 0);
    float4 ap; if (tid < 128) ap = loadA4(0);

    for (int kt=0; kt<NKT; kt++){
        // store current tile into smem
        { int crow=tid>>2, kk=(tid&3)*4;
          Bs[kk][crow]=bp0.x; Bs[kk+1][crow]=bp0.y; Bs[kk+2][crow]=bp0.z; Bs[kk+3][crow]=bp0.w; }
        { int e=tid+256; int crow=e>>2, kk=(e&3)*4;
          Bs[kk][crow]=bp1.x; Bs[kk+1][crow]=bp1.y; Bs[kk+2][crow]=bp1.z; Bs[kk+3][crow]=bp1.w; }
        if (tid < 128){
            int r=tid>>2, kk=(tid&3)*4;
            As[kk][r]=ap.x; As[kk+1][r]=ap.y; As[kk+2][r]=ap.z; As[kk+3][r]=ap.w;
        }
        __syncthreads();

        // prefetch next tile (overlaps with compute below)
        if (kt+1 < NKT){
            int k0 = (kt+1)*16;
            bp0 = loadB4(tid, k0); bp1 = loadB4(tid+256, k0);
            if (tid < 128) ap = loadA4(k0);
        }

        #pragma unroll
        for (int kk=0; kk<16; kk++){
            float2 av  = *(const float2*)&As[kk][2*tr];
            float4 bv0 = *(const float4*)&Bs[kk][cg*8];
            float4 bv1 = *(const float4*)&Bs[kk][cg*8+4];
            acc[0][0] += av.x*bv0.x; acc[0][1] += av.x*bv0.y;
            acc[0][2] += av.x*bv0.z; acc[0][3] += av.x*bv0.w;
            acc[0][4] += av.x*bv1.x; acc[0][5] += av.x*bv1.y;
            acc[0][6] += av.x*bv1.z; acc[0][7] += av.x*bv1.w;
            acc[1][0] += av.y*bv0.x; acc[1][1] += av.y*bv0.y;
            acc[1][2] += av.y*bv0.z; acc[1][3] += av.y*bv0.w;
            acc[1][4] += av.y*bv1.x; acc[1][5] += av.y*bv1.y;
            acc[1][6] += av.y*bv1.z; acc[1][7] += av.y*bv1.w;
        }
        __syncthreads();
    }

    // spill z tile to smem, then do the gate math per (b,h) element
    #pragma unroll
    for (int ii=0; ii<2; ii++)
        #pragma unroll
        for (int u=0; u<8; u++)
            zs[(2*tr+ii)*128 + cg*8 + u] = acc[ii][u];
    __syncthreads();

    #pragma unroll
    for (int q=0; q<4; q++){
        int p = tid + q*256;           // 0..1023 -> (r,j)
        int r = p >> 5, j = p & 31;
        int bg = b0 + r, hg = h0 + j;
        float zi = zs[r*128 +       j] + bias[         hg];
        float zf = zs[r*128 + 32 +  j] + bias[Hn     + hg];
        float zg = zs[r*128 + 64 +  j] + bias[2*Hn   + hg];
        float zo = zs[r*128 + 96 +  j] + bias[3*Hn   + hg];
        float cold = g_c[bg*Hn + hg];
        float cn = sigmoidf_(zf)*cold + sigmoidf_(zi)*tanhf(zg);
        g_c[bg*Hn + hg] = cn;
        float hn = sigmoidf_(zo)*tanhf(cn);
        h_out[bg*Hn + hg] = hn;
        if (ENC) g_enc_out[((size_t)t*Bn + bg)*Hn + hg] = hn;
    }
}

// ---------------------------------------------------------------------------
// enc_score[s][b] = dot(enc_out[s,b,:], Wf[0:H]) ; one warp per (s,b)
// ---------------------------------------------------------------------------
__global__ void enc_score_k(const float* __restrict__ Wf){
    int w    = (blockIdx.x*blockDim.x + threadIdx.x) >> 5;
    int lane = threadIdx.x & 31;
    int s = w >> 8, b = w & 255;
    const float* row = g_enc_out + ((size_t)s*Bn + b)*Hn;
    float acc = 0.f;
    for (int h = lane; h < Hn; h += 32) acc += row[h]*Wf[h];
    #pragma unroll
    for (int o=16;o;o>>=1) acc += __shfl_down_sync(0xffffffffu, acc, o);
    if (lane==0) g_enc_score[s*Bn + b] = acc;
}

// ---------------------------------------------------------------------------
// Attention + output heads + argmax feedback. One block per batch row.
// ---------------------------------------------------------------------------
__global__ __launch_bounds__(256) void attn_k(
    const float* __restrict__ Wf, const float* __restrict__ bfv,
    const float* __restrict__ W_a, const float* __restrict__ b_a,
    const float* __restrict__ W_t, const float* __restrict__ b_t,
    float* __restrict__ out, int t, int par)
{
    __shared__ float sh_w[Sn];
    __shared__ float sh_ctx[Hn];
    __shared__ float red[256];
    __shared__ float sh_p[An+NTn];

    const int b = blockIdx.x, tid = threadIdx.x;
    const float* h = g_h[par] + b*Hn;

    // h . Wd (constant shift per b; kept for numerical fidelity with reference)
    float part = h[tid]*Wf[Hn+tid] + h[tid+256]*Wf[Hn+tid+256];
    red[tid] = part; __syncthreads();
    for (int o=128;o;o>>=1){ if (tid<o) red[tid]+=red[tid+o]; __syncthreads(); }
    float hdot = red[0] + bfv[0];
    __syncthreads();

    // softmax over s
    float sc = g_enc_score[tid*Bn + b] + hdot;
    red[tid] = sc; __syncthreads();
    for (int o=128;o;o>>=1){ if (tid<o) red[tid]=fmaxf(red[tid],red[tid+o]); __syncthreads(); }
    float m = red[0]; __syncthreads();
    float e = expf(sc - m);
    red[tid] = e; __syncthreads();
    for (int o=128;o;o>>=1){ if (tid<o) red[tid]+=red[tid+o]; __syncthreads(); }
    float inv = 1.f/red[0];
    __syncthreads();
    sh_w[tid] = e*inv;
    __syncthreads();

    // ctx[b,:] = sum_s w[s] * enc_out[s,b,:]
    float a0=0.f, a1=0.f;
    const float* base = g_enc_out + (size_t)b*Hn;
    for (int s=0; s<Sn; s++){
        float ws = sh_w[s];
        const float* row = base + (size_t)s*Bn*Hn;
        a0 += ws*row[tid]; a1 += ws*row[tid+256];
    }
    sh_ctx[tid]=a0; sh_ctx[tid+256]=a1;
    __syncthreads();

    // output heads
    if (tid < An){
        float acc = b_a[tid];
        const float* w = W_a + tid*Hn;
        #pragma unroll 8
        for (int k=0;k<Hn;k++) acc += sh_ctx[k]*w[k];
        sh_p[tid] = acc;
        out[(b*Tn + t)*An + tid] = acc;
    } else if (tid < An+NTn){
        int j = tid - An;
        float acc = b_t[j];
        const float* w = W_t + j*Hn;
        #pragma unroll 8
        for (int k=0;k<Hn;k++) acc += sh_ctx[k]*w[k];
        sh_p[tid] = acc;
        out[Bn*Tn*An + (b*Tn + t)*NTn + j] = acc;
    }
    __syncthreads();

    if (tid==0){
        int ia=0; float bv=sh_p[0];
        #pragma unroll
        for (int a=1;a<An;a++) if (sh_p[a]>bv){bv=sh_p[a]; ia=a;}
        int it=0; float tv=sh_p[An];
        for (int j=1;j<NTn;j++) if (sh_p[An+j]>tv){tv=sh_p[An+j]; it=j;}
        g_inp[b*2]   = ia;
        g_inp[b*2+1] = it;
    }
}

extern "C" void kernel_launch(void* const* d_in, const int* in_sizes, int n_in,
                              void* d_out, int out_size)
{
    const int*   enc_input = (const int*)  d_in[0];
    // d_in[1] = decoder_target (unused by reference)
    const float* enc_embed = (const float*)d_in[2];
    const float* Wi_e      = (const float*)d_in[3];
    const float* Wh_e      = (const float*)d_in[4];
    const float* b_e       = (const float*)d_in[5];
    const float* act_emb   = (const float*)d_in[6];
    const float* tgt_emb   = (const float*)d_in[7];
    const float* Wi_d      = (const float*)d_in[8];
    const float* Wh_d      = (const float*)d_in[9];
    const float* b_d       = (const float*)d_in[10];
    const float* W_a       = (const float*)d_in[11];
    const float* b_a       = (const float*)d_in[12];
    const float* W_t       = (const float*)d_in[13];
    const float* b_t       = (const float*)d_in[14];
    const float* Wf        = (const float*)d_in[15];
    const float* bf        = (const float*)d_in[16];
    float* out = (float*)d_out;

    init_k<<<(Bn*Hn + 255)/256, 256>>>();

    for (int t=0; t<Sn; t++)
        lstm_k<En, true><<<128, 256>>>(Wi_e, Wh_e, b_e,
                                       enc_input, enc_embed, nullptr, nullptr,
                                       t, t & 1);

    enc_score_k<<<(Sn*Bn)/8, 256>>>(Wf);

    for (int t=0; t<Tn; t++){
        lstm_k<2*EDn, false><<<128, 256>>>(Wi_d, Wh_d, b_d,
                                           nullptr, nullptr, act_emb, tgt_emb,
                                           t, t & 1);
        attn_k<<<Bn, 256>>>(Wf, bf, W_a, b_a, W_t, b_t, out, t, (t & 1) ^ 1);
    }
}

// round 6
// speedup vs baseline: 2.1290x; 2.1290x over previous
#include <cuda_runtime.h>
#include <math.h>
#include <stdint.h>

#define Bn 256
#define Sn 256
#define Tn 32
#define Hn 512
#define En 128
#define EDn 32
#define An 8
#define NTn 80

__device__ float g_h[2][Bn*Hn];
__device__ float g_c[Bn*Hn];
__device__ float g_enc_out[(size_t)Sn*Bn*Hn];
__device__ float g_zx[1000*4*Hn];
__device__ float g_act_z[An*4*Hn];
__device__ float g_tgt_z[NTn*4*Hn];
__device__ float g_P[(size_t)Sn*Bn*96];
__device__ float g_wpad[128*Hn];
__device__ float g_wie_r[4*Hn*En];
__device__ float g_whe_r[4*Hn*Hn];
__device__ float g_whd_r[4*Hn*Hn];
__device__ float g_emb_r[1000*En];
__device__ int   g_inp[Bn*2];

__device__ __forceinline__ float sigmoidf_(float x){ return 1.f/(1.f+expf(-x)); }
__device__ __forceinline__ float rna_f(float x){
    uint32_t u; asm("cvt.rna.tf32.f32 %0, %1;" : "=r"(u) : "f"(x));
    return __uint_as_float(u);
}
__device__ __forceinline__ uint32_t smem_u32(const void* p){
    uint32_t a;
    asm("{ .reg .u64 t; cvta.to.shared.u64 t, %1; cvt.u32.u64 %0, t; }" : "=r"(a) : "l"(p));
    return a;
}
#define CP_ASYNC16(dst, src) \
    asm volatile("cp.async.cg.shared.global [%0], [%1], 16;" :: "r"(dst), "l"(src))
#define CP_COMMIT() asm volatile("cp.async.commit_group;" ::: "memory")
#define CP_WAIT(n)  asm volatile("cp.async.wait_group %0;" :: "n"(n) : "memory")
#define MMA_TF32(d, a, b0v, b1v) \
    asm volatile("mma.sync.aligned.m16n8k8.row.col.f32.tf32.tf32.f32 " \
        "{%0,%1,%2,%3}, {%4,%5,%6,%7}, {%8,%9}, {%0,%1,%2,%3};" \
        : "+f"((d)[0]),"+f"((d)[1]),"+f"((d)[2]),"+f"((d)[3]) \
        : "r"((a)[0]),"r"((a)[1]),"r"((a)[2]),"r"((a)[3]), "r"(b0v),"r"(b1v))

__global__ void init_k(){
    int i = blockIdx.x*blockDim.x + threadIdx.x;
    if (i < Bn*Hn){ g_h[0][i]=0.f; g_h[1][i]=0.f; g_c[i]=0.f; }
    if (i < Bn*2) g_inp[i]=0;
}
__global__ void round_k(const float* __restrict__ s, float* __restrict__ d, int n){
    int i = blockIdx.x*blockDim.x + threadIdx.x;
    if (i < n) d[i] = rna_f(s[i]);
}
__global__ void build_wpad_k(const float* __restrict__ W_a, const float* __restrict__ W_t,
                             const float* __restrict__ Wf){
    int i = blockIdx.x*blockDim.x + threadIdx.x;
    if (i >= 128*Hn) return;
    int r = i >> 9, k = i & 511;
    float v = 0.f;
    if (r < 8)        v = W_a[r*Hn + k];
    else if (r < 88)  v = W_t[(r-8)*Hn + k];
    else if (r == 88) v = Wf[k];
    g_wpad[i] = rna_f(v);
}
__global__ void build_dec_tables_k(const float* __restrict__ act_emb,
                                   const float* __restrict__ tgt_emb,
                                   const float* __restrict__ Wi_d){
    int i = blockIdx.x*blockDim.x + threadIdx.x;
    if (i >= 88*4*Hn) return;
    int r = i >> 11, col = i & 2047;
    if (r < An){
        float a = 0.f; const float* w = Wi_d + col*64; const float* e = act_emb + r*EDn;
        #pragma unroll
        for (int k=0;k<EDn;k++) a += e[k]*w[k];
        g_act_z[r*4*Hn + col] = a;
    } else {
        r -= An;
        float a = 0.f; const float* w = Wi_d + col*64 + EDn; const float* e = tgt_emb + r*EDn;
        #pragma unroll
        for (int k=0;k<EDn;k++) a += e[k]*w[k];
        g_tgt_z[r*4*Hn + col] = a;
    }
}

// MODE 0: zx = emb·Wi_e^T (K=128)   MODE 1: enc step (K=512)
// MODE 2: dec step (K=512)          MODE 3: P = enc_out·Wpad^T (K=512)
// CTA: 128 threads (4 warps, 2m x 2n), tile 128x128, warp 64x64.
template<int MODE>
__global__ __launch_bounds__(128,1) void tc_k(
    const float* __restrict__ bias, const int* __restrict__ enc_input,
    int t, int par)
{
    constexpr int NC = (MODE==0) ? 4 : 16;
    extern __shared__ __align__(1024) uint32_t dsm[];

    const int tid = threadIdx.x;
    const int lane = tid & 31, warp = tid >> 5;
    const int wm = warp >> 1, wn = warp & 1;
    const int c4 = lane & 3, r4 = lane >> 2;
    const int nIdx = blockIdx.x;
    const int m0   = blockIdx.y * 128;
    const float* hin = g_h[par];

    float acc[4][8][4];
    #pragma unroll
    for (int i=0;i<4;i++)
        #pragma unroll
        for (int j=0;j<8;j++)
            #pragma unroll
            for (int q=0;q<4;q++) acc[i][j][q]=0.f;

    auto aRow = [&](int m)->const float* {
        if (MODE==0){ int rr=m0+m; if(rr>999) rr=999; return g_emb_r + (size_t)rr*En; }
        if (MODE==3) return g_enc_out + (size_t)(m0+m)*Hn;
        return hin + (size_t)(m0+m)*Hn;
    };
    auto bRow = [&](int rn)->const float* {
        if (MODE==0) return g_wie_r + (size_t)(nIdx*128 + rn)*En;
        if (MODE==3) return g_wpad + (size_t)rn*Hn;
        const float* W = (MODE==1) ? g_whe_r : g_whd_r;
        return W + (size_t)((rn>>5)*Hn + nIdx*32 + (rn&31))*Hn;
    };
    const uint32_t smb = smem_u32(dsm);
    auto load_chunk = [&](int c, int st){
        uint32_t base = smb + (uint32_t)st*32768u;
        int k0 = c*32;
        #pragma unroll
        for (int i=0;i<8;i++){
            int u = tid + i*128;
            int m = u>>3, g = u&7;
            CP_ASYNC16(base + (uint32_t)(m*128 + ((g^(m&7))<<4)), aRow(m) + k0 + g*4);
        }
        #pragma unroll
        for (int i=0;i<8;i++){
            int u = tid + i*128;
            int rn = u>>3, g = u&7;
            CP_ASYNC16(base + 16384u + (uint32_t)(rn*128 + ((g^(rn&7))<<4)), bRow(rn) + k0 + g*4);
        }
        CP_COMMIT();
    };

    load_chunk(0,0);
    load_chunk(1,1);

    #pragma unroll 1
    for (int c=0;c<NC;c++){
        if (c+2 < NC) load_chunk(c+2, (c+2)%3);
        if (c+2 < NC) { CP_WAIT(2); } else if (c+1 < NC) { CP_WAIT(1); } else { CP_WAIT(0); }
        __syncthreads();
        const uint32_t* S = dsm + (c%3)*8192;
        #pragma unroll
        for (int ks=0;ks<4;ks++){
            int sw0 = (((2*ks  ) ^ r4) << 2) + c4;
            int sw1 = (((2*ks+1) ^ r4) << 2) + c4;
            uint32_t a[4][4];
            #pragma unroll
            for (int i=0;i<4;i++){
                int r0 = (wm*64 + i*16 + r4)*32;
                int r8 = r0 + 256;
                a[i][0]=S[r0+sw0]; a[i][1]=S[r8+sw0];
                a[i][2]=S[r0+sw1]; a[i][3]=S[r8+sw1];
            }
            #pragma unroll
            for (int j=0;j<8;j++){
                int nb = (MODE==1 || MODE==2) ? ((j>>1)*32 + wn*16 + (j&1)*8)
                                              : (wn*64 + j*8);
                int n0 = 4096 + (nb + r4)*32;
                uint32_t b0 = S[n0+sw0], b1 = S[n0+sw1];
                #pragma unroll
                for (int i=0;i<4;i++)
                    MMA_TF32(acc[i][j], a[i], b0, b1);
            }
        }
        __syncthreads();
    }

    if (MODE==0 || MODE==3){
        #pragma unroll
        for (int i=0;i<4;i++)
        #pragma unroll
        for (int rh=0;rh<2;rh++){
            int gm = m0 + wm*64 + i*16 + rh*8 + r4;
            #pragma unroll
            for (int j=0;j<8;j++)
            #pragma unroll
            for (int cc=0;cc<2;cc++){
                int col = wn*64 + j*8 + c4*2 + cc;
                float v = acc[i][j][rh*2+cc];
                if (MODE==0){
                    if (gm < 1000) g_zx[(size_t)gm*2048 + nIdx*128 + col] = v;
                } else {
                    if (col < 96) g_P[(size_t)gm*96 + col] = v;
                }
            }
        }
    } else {
        #pragma unroll
        for (int i=0;i<4;i++)
        #pragma unroll
        for (int rh=0;rh<2;rh++){
            int bg = m0 + wm*64 + i*16 + rh*8 + r4;
            const float *x0, *x1 = nullptr;
            if (MODE==1){ x0 = g_zx + (size_t)enc_input[bg*Sn + t]*2048; }
            else { x0 = g_act_z + (size_t)g_inp[bg*2]*2048;
                   x1 = g_tgt_z + (size_t)g_inp[bg*2+1]*2048; }
            float* hout = g_h[par^1] + (size_t)bg*Hn;
            float* crow = g_c + (size_t)bg*Hn;
            float* eout = g_enc_out + ((size_t)t*Bn + bg)*Hn;
            #pragma unroll
            for (int jj=0;jj<2;jj++)
            #pragma unroll
            for (int cc=0;cc<2;cc++){
                int u = nIdx*32 + wn*16 + jj*8 + c4*2 + cc;
                int q = rh*2 + cc;
                float xi, xf, xg, xo;
                if (MODE==1){ xi=x0[u]; xf=x0[512+u]; xg=x0[1024+u]; xo=x0[1536+u]; }
                else { xi=x0[u]+x1[u]; xf=x0[512+u]+x1[512+u];
                       xg=x0[1024+u]+x1[1024+u]; xo=x0[1536+u]+x1[1536+u]; }
                float zi = acc[i][  jj][q] + bias[       u] + xi;
                float zf = acc[i][2+jj][q] + bias[ 512 + u] + xf;
                float zg = acc[i][4+jj][q] + bias[1024 + u] + xg;
                float zo = acc[i][6+jj][q] + bias[1536 + u] + xo;
                float co = crow[u];
                float cn = sigmoidf_(zf)*co + sigmoidf_(zi)*tanhf(zg);
                crow[u] = cn;
                float hn = rna_f(sigmoidf_(zo)*tanhf(cn));
                hout[u] = hn;
                if (MODE==1) eout[u] = hn;
            }
        }
    }
}

__global__ __launch_bounds__(128) void attn2_k(
    const float* __restrict__ Wf, const float* __restrict__ bfv,
    const float* __restrict__ b_a, const float* __restrict__ b_t,
    float* __restrict__ out, int t, int par)
{
    __shared__ float shw[Sn];
    __shared__ float red[128];
    __shared__ float shp[96];
    const int b = blockIdx.x, tid = threadIdx.x;
    const float* h = g_h[par] + (size_t)b*Hn;

    float part = 0.f;
    for (int k=tid;k<Hn;k+=128) part += h[k]*Wf[Hn+k];
    red[tid]=part; __syncthreads();
    for (int o=64;o;o>>=1){ if (tid<o) red[tid]+=red[tid+o]; __syncthreads(); }
    float hdot = red[0] + bfv[0];
    __syncthreads();

    float sc0 = g_P[((size_t)tid      *Bn + b)*96 + 88] + hdot;
    float sc1 = g_P[((size_t)(tid+128)*Bn + b)*96 + 88] + hdot;
    red[tid] = fmaxf(sc0, sc1); __syncthreads();
    for (int o=64;o;o>>=1){ if (tid<o) red[tid]=fmaxf(red[tid],red[tid+o]); __syncthreads(); }
    float m = red[0]; __syncthreads();
    float e0 = expf(sc0-m), e1 = expf(sc1-m);
    red[tid] = e0+e1; __syncthreads();
    for (int o=64;o;o>>=1){ if (tid<o) red[tid]+=red[tid+o]; __syncthreads(); }
    float inv = 1.f/red[0];
    shw[tid] = e0*inv; shw[tid+128] = e1*inv;
    __syncthreads();

    if (tid < 88){
        float acc = 0.f;
        const float* pb = g_P + (size_t)b*96 + tid;
        const size_t stride = (size_t)Bn*96;
        #pragma unroll 4
        for (int s=0;s<Sn;s++) acc += shw[s]*pb[(size_t)s*stride];
        acc += (tid < An) ? b_a[tid] : b_t[tid-An];
        shp[tid] = acc;
        if (tid < An) out[(b*Tn + t)*An + tid] = acc;
        else          out[Bn*Tn*An + (b*Tn + t)*NTn + (tid-An)] = acc;
    }
    __syncthreads();
    if (tid == 0){
        int ia=0; float bv=shp[0];
        #pragma unroll
        for (int a=1;a<An;a++) if (shp[a]>bv){bv=shp[a]; ia=a;}
        int it=0; float tv=shp[An];
        for (int j=1;j<NTn;j++) if (shp[An+j]>tv){tv=shp[An+j]; it=j;}
        g_inp[b*2] = ia; g_inp[b*2+1] = it;
    }
}

extern "C" void kernel_launch(void* const* d_in, const int* in_sizes, int n_in,
                              void* d_out, int out_size)
{
    const int*   enc_input = (const int*)  d_in[0];
    const float* enc_embed = (const float*)d_in[2];
    const float* Wi_e      = (const float*)d_in[3];
    const float* Wh_e      = (const float*)d_in[4];
    const float* b_e       = (const float*)d_in[5];
    const float* act_emb   = (const float*)d_in[6];
    const float* tgt_emb   = (const float*)d_in[7];
    const float* Wi_d      = (const float*)d_in[8];
    const float* Wh_d      = (const float*)d_in[9];
    const float* b_d       = (const float*)d_in[10];
    const float* W_a       = (const float*)d_in[11];
    const float* b_a       = (const float*)d_in[12];
    const float* W_t       = (const float*)d_in[13];
    const float* b_t       = (const float*)d_in[14];
    const float* Wf        = (const float*)d_in[15];
    const float* bf        = (const float*)d_in[16];
    float* out = (float*)d_out;

    const int SMEM_SZ = 3*32768;
    cudaFuncSetAttribute(tc_k<0>, cudaFuncAttributeMaxDynamicSharedMemorySize, SMEM_SZ);
    cudaFuncSetAttribute(tc_k<1>, cudaFuncAttributeMaxDynamicSharedMemorySize, SMEM_SZ);
    cudaFuncSetAttribute(tc_k<2>, cudaFuncAttributeMaxDynamicSharedMemorySize, SMEM_SZ);
    cudaFuncSetAttribute(tc_k<3>, cudaFuncAttributeMaxDynamicSharedMemorySize, SMEM_SZ);

    init_k<<<(Bn*Hn + 255)/256, 256>>>();

    float* whe_r; cudaGetSymbolAddress((void**)&whe_r, g_whe_r);
    float* whd_r; cudaGetSymbolAddress((void**)&whd_r, g_whd_r);
    float* wie_r; cudaGetSymbolAddress((void**)&wie_r, g_wie_r);
    float* emb_r; cudaGetSymbolAddress((void**)&emb_r, g_emb_r);
    round_k<<<(4*Hn*Hn + 255)/256, 256>>>(Wh_e, whe_r, 4*Hn*Hn);
    round_k<<<(4*Hn*Hn + 255)/256, 256>>>(Wh_d, whd_r, 4*Hn*Hn);
    round_k<<<(4*Hn*En + 255)/256, 256>>>(Wi_e, wie_r, 4*Hn*En);
    round_k<<<(1000*En + 255)/256, 256>>>(enc_embed, emb_r, 1000*En);

    build_wpad_k<<<(128*Hn + 255)/256, 256>>>(W_a, W_t, Wf);
    build_dec_tables_k<<<(88*4*Hn + 255)/256, 256>>>(act_emb, tgt_emb, Wi_d);

    // zx table: emb_r @ Wi_e_r^T
    tc_k<0><<<dim3(16,8), 128, SMEM_SZ>>>(nullptr, nullptr, 0, 0);

    // encoder recurrence
    for (int t=0; t<Sn; t++)
        tc_k<1><<<dim3(16,2), 128, SMEM_SZ>>>(b_e, enc_input, t, t & 1);

    // projections P = enc_out @ wpad^T
    tc_k<3><<<dim3(1,512), 128, SMEM_SZ>>>(nullptr, nullptr, 0, 0);

    // decoder
    for (int t=0; t<Tn; t++){
        tc_k<2><<<dim3(16,2), 128, SMEM_SZ>>>(b_d, nullptr, t, t & 1);
        attn2_k<<<Bn, 128>>>(Wf, bf, b_a, b_t, out, t, (t & 1) ^ 1);
    }
}

// round 8
// speedup vs baseline: 3.6672x; 1.7225x over previous
#include <cuda_runtime.h>
#include <math.h>
#include <stdint.h>

#define Bn 256
#define Sn 256
#define Tn 32
#define Hn 512
#define En 128
#define EDn 32
#define An 8
#define NTn 80

__device__ float g_h[2][Bn*Hn];
__device__ float g_c[Bn*Hn];
__device__ float g_enc_out[(size_t)Sn*Bn*Hn];
__device__ float g_zx[1000*4*Hn];
__device__ float g_act_z[An*4*Hn];
__device__ float g_tgt_z[NTn*4*Hn];
__device__ float g_P[(size_t)Sn*Bn*96];
__device__ float g_wpad[128*Hn];
__device__ float g_wie_r[4*Hn*En];
__device__ float g_whe_r[4*Hn*Hn];
__device__ float g_whd_r[4*Hn*Hn];
__device__ float g_emb_r[1000*En];
__device__ int   g_inp[Bn*2];
__device__ int   g_bar[384];

__device__ __forceinline__ float sigmoidf_(float x){ return 1.f/(1.f+expf(-x)); }
__device__ __forceinline__ float rna_f(float x){
    uint32_t u; asm("cvt.rna.tf32.f32 %0, %1;" : "=r"(u) : "f"(x));
    return __uint_as_float(u);
}
__device__ __forceinline__ uint32_t smem_u32(const void* p){
    uint32_t a;
    asm("{ .reg .u64 t; cvta.to.shared.u64 t, %1; cvt.u32.u64 %0, t; }" : "=r"(a) : "l"(p));
    return a;
}
#define CP_ASYNC16(dst, src) \
    asm volatile("cp.async.cg.shared.global [%0], [%1], 16;" :: "r"(dst), "l"(src))
#define CP_COMMIT() asm volatile("cp.async.commit_group;" ::: "memory")
#define CP_WAIT(n)  asm volatile("cp.async.wait_group %0;" :: "n"(n) : "memory")
#define MMA_TF32(d, a, b0v, b1v) \
    asm volatile("mma.sync.aligned.m16n8k8.row.col.f32.tf32.tf32.f32 " \
        "{%0,%1,%2,%3}, {%4,%5,%6,%7}, {%8,%9}, {%0,%1,%2,%3};" \
        : "+f"((d)[0]),"+f"((d)[1]),"+f"((d)[2]),"+f"((d)[3]) \
        : "r"((a)[0]),"r"((a)[1]),"r"((a)[2]),"r"((a)[3]), "r"(b0v),"r"(b1v))

// grid-wide barrier (all CTAs resident; per-step counter, reset by init_k)
__device__ __forceinline__ void gbar(int idx, int nc){
    __syncthreads();
    if (threadIdx.x == 0){
        int* p = &g_bar[idx];
        asm volatile("red.release.gpu.global.add.u32 [%0], 1;" :: "l"(p) : "memory");
        uint32_t v;
        do {
            asm volatile("ld.acquire.gpu.global.u32 %0, [%1];" : "=r"(v) : "l"(p) : "memory");
        } while (v < (uint32_t)nc);
    }
    __syncthreads();
}

__global__ void init_k(){
    int i = blockIdx.x*blockDim.x + threadIdx.x;
    if (i < Bn*Hn){ g_h[0][i]=0.f; g_h[1][i]=0.f; g_c[i]=0.f; }
    if (i < Bn*2) g_inp[i]=0;
    if (i < 384)  g_bar[i]=0;
}
__global__ void round_k(const float* __restrict__ s, float* __restrict__ d, int n){
    int i = blockIdx.x*blockDim.x + threadIdx.x;
    if (i < n) d[i] = rna_f(s[i]);
}
__global__ void build_wpad_k(const float* __restrict__ W_a, const float* __restrict__ W_t,
                             const float* __restrict__ Wf){
    int i = blockIdx.x*blockDim.x + threadIdx.x;
    if (i >= 128*Hn) return;
    int r = i >> 9, k = i & 511;
    float v = 0.f;
    if (r < 8)        v = W_a[r*Hn + k];
    else if (r < 88)  v = W_t[(r-8)*Hn + k];
    else if (r == 88) v = Wf[k];
    g_wpad[i] = rna_f(v);
}
__global__ void build_dec_tables_k(const float* __restrict__ act_emb,
                                   const float* __restrict__ tgt_emb,
                                   const float* __restrict__ Wi_d){
    int i = blockIdx.x*blockDim.x + threadIdx.x;
    if (i >= 88*4*Hn) return;
    int r = i >> 11, col = i & 2047;
    if (r < An){
        float a = 0.f; const float* w = Wi_d + col*64; const float* e = act_emb + r*EDn;
        #pragma unroll
        for (int k=0;k<EDn;k++) a += e[k]*w[k];
        g_act_z[r*4*Hn + col] = a;
    } else {
        r -= An;
        float a = 0.f; const float* w = Wi_d + col*64 + EDn; const float* e = tgt_emb + r*EDn;
        #pragma unroll
        for (int k=0;k<EDn;k++) a += e[k]*w[k];
        g_tgt_z[r*4*Hn + col] = a;
    }
}

// ---------------------------------------------------------------------------
// 64x128 tile GEMM core. 256 threads = 8 warps: wm(2) x wn(4).
// Warp tile: 32 rows x 32 cols; gate-interleaved col map for MODE 1/2.
// MODE 0: zx = emb·Wi_e^T (K=128). 1: enc step. 2: dec step. 3: P (K=512).
// smem/chunk stage: A 64x32f (8KB) + B 128x32f (16KB) = 24KB, 3 stages.
// ---------------------------------------------------------------------------
template<int MODE>
__device__ __forceinline__ void gemm_tile(uint32_t* dsm, const float* __restrict__ Ap,
                                          int nIdx, int m0, float (&acc)[2][4][4])
{
    constexpr int NC = (MODE==0) ? 4 : 16;
    const int tid = threadIdx.x;
    const int lane = tid & 31, warp = tid >> 5;
    const int wm = warp >> 2, wn = warp & 3;
    const int c4 = lane & 3, r4 = lane >> 2;

    #pragma unroll
    for (int i=0;i<2;i++)
        #pragma unroll
        for (int j=0;j<4;j++)
            #pragma unroll
            for (int q=0;q<4;q++) acc[i][j][q]=0.f;

    auto aRow = [&](int m)->const float* {
        if (MODE==0){ int rr=m0+m; if (rr>999) rr=999; return Ap + (size_t)rr*En; }
        return Ap + (size_t)(m0+m)*Hn;
    };
    auto bRow = [&](int rn)->const float* {
        if (MODE==0) return g_wie_r + (size_t)(nIdx*128 + rn)*En;
        if (MODE==3) return g_wpad + (size_t)rn*Hn;
        const float* W = (MODE==1) ? g_whe_r : g_whd_r;
        return W + (size_t)((rn>>5)*Hn + nIdx*32 + (rn&31))*Hn;
    };
    const uint32_t smb = smem_u32(dsm);
    auto load_chunk = [&](int c, int st){
        uint32_t base = smb + (uint32_t)st*24576u;
        int k0 = c*32;
        #pragma unroll
        for (int i=0;i<2;i++){
            int u = tid + i*256;
            int m = u>>3, g = u&7;
            CP_ASYNC16(base + (uint32_t)(m*128 + ((g^(m&7))<<4)), aRow(m) + k0 + g*4);
        }
        #pragma unroll
        for (int i=0;i<4;i++){
            int u = tid + i*256;
            int rn = u>>3, g = u&7;
            CP_ASYNC16(base + 8192u + (uint32_t)(rn*128 + ((g^(rn&7))<<4)), bRow(rn) + k0 + g*4);
        }
        CP_COMMIT();
    };

    load_chunk(0,0);
    load_chunk(1,1);

    #pragma unroll 1
    for (int c=0;c<NC;c++){
        if (c+2 < NC) load_chunk(c+2, (c+2)%3);
        if (c+2 < NC) { CP_WAIT(2); } else if (c+1 < NC) { CP_WAIT(1); } else { CP_WAIT(0); }
        __syncthreads();
        const uint32_t* S = dsm + (c%3)*6144;
        #pragma unroll
        for (int ks=0;ks<4;ks++){
            int sw0 = (((2*ks  ) ^ r4) << 2) + c4;
            int sw1 = (((2*ks+1) ^ r4) << 2) + c4;
            uint32_t a[2][4];
            #pragma unroll
            for (int i=0;i<2;i++){
                int r0 = (wm*32 + i*16 + r4)*32;
                a[i][0]=S[r0+sw0]; a[i][1]=S[r0+256+sw0];
                a[i][2]=S[r0+sw1]; a[i][3]=S[r0+256+sw1];
            }
            #pragma unroll
            for (int j=0;j<4;j++){
                int nb = (MODE==1 || MODE==2) ? (j*32 + wn*8) : (wn*32 + j*8);
                int n0 = 2048 + (nb + r4)*32;
                uint32_t b0 = S[n0+sw0], b1 = S[n0+sw1];
                MMA_TF32(acc[0][j], a[0], b0, b1);
                MMA_TF32(acc[1][j], a[1], b0, b1);
            }
        }
        __syncthreads();
    }
}

template<int MODE>
__device__ __forceinline__ void lstm_epi(float (&acc)[2][4][4], const float* __restrict__ bias,
                                         const int* __restrict__ enc_input,
                                         int nIdx, int m0, int t, int par)
{
    const int lane = threadIdx.x & 31, warp = threadIdx.x >> 5;
    const int wm = warp >> 2, wn = warp & 3;
    const int c4 = lane & 3, r4 = lane >> 2;
    #pragma unroll
    for (int i=0;i<2;i++)
    #pragma unroll
    for (int rh=0;rh<2;rh++){
        int bg = m0 + wm*32 + i*16 + rh*8 + r4;
        const float *x0, *x1 = nullptr;
        if (MODE==1){ x0 = g_zx + (size_t)enc_input[bg*Sn + t]*2048; }
        else { x0 = g_act_z + (size_t)g_inp[bg*2]*2048;
               x1 = g_tgt_z + (size_t)g_inp[bg*2+1]*2048; }
        float* hout = g_h[par^1] + (size_t)bg*Hn;
        float* crow = g_c + (size_t)bg*Hn;
        float* eout = g_enc_out + ((size_t)t*Bn + bg)*Hn;
        #pragma unroll
        for (int cc=0;cc<2;cc++){
            int u = nIdx*32 + wn*8 + c4*2 + cc;
            int q = rh*2 + cc;
            float xi, xf, xg, xo;
            if (MODE==1){ xi=x0[u]; xf=x0[512+u]; xg=x0[1024+u]; xo=x0[1536+u]; }
            else { xi=x0[u]+x1[u]; xf=x0[512+u]+x1[512+u];
                   xg=x0[1024+u]+x1[1024+u]; xo=x0[1536+u]+x1[1536+u]; }
            float zi = acc[i][0][q] + bias[       u] + xi;
            float zf = acc[i][1][q] + bias[ 512 + u] + xf;
            float zg = acc[i][2][q] + bias[1024 + u] + xg;
            float zo = acc[i][3][q] + bias[1536 + u] + xo;
            float co = crow[u];
            float cn = sigmoidf_(zf)*co + sigmoidf_(zi)*tanhf(zg);
            crow[u] = cn;
            float hn = rna_f(sigmoidf_(zo)*tanhf(cn));
            hout[u] = hn;
            if (MODE==1) eout[u] = hn;
        }
    }
}

// persistent encoder: 64 CTAs x 256 thr, 256 steps with grid barrier
__global__ __launch_bounds__(256,1) void enc_persist_k(
    const float* __restrict__ bias, const int* __restrict__ enc_input)
{
    extern __shared__ __align__(1024) uint32_t dsm[];
    const int nIdx = blockIdx.x >> 2;
    const int m0   = (blockIdx.x & 3) * 64;
    float acc[2][4][4];
    for (int t=0;t<Sn;t++){
        int par = t & 1;
        gemm_tile<1>(dsm, g_h[par], nIdx, m0, acc);
        lstm_epi<1>(acc, bias, enc_input, nIdx, m0, t, par);
        gbar(t, 64);
    }
}

__device__ __forceinline__ void attn_row(
    int b, int t, int par,
    const float* __restrict__ Wf, const float* __restrict__ bfv,
    const float* __restrict__ b_a, const float* __restrict__ b_t,
    float* __restrict__ out,
    float* shw, float* red, float* pp, float* shp)
{
    const int tid = threadIdx.x;
    const float* h = g_h[par] + (size_t)b*Hn;

    float part = h[tid]*Wf[512+tid] + h[tid+256]*Wf[768+tid];
    red[tid] = part; __syncthreads();
    for (int o=128;o;o>>=1){ if (tid<o) red[tid]+=red[tid+o]; __syncthreads(); }
    float hdot = red[0] + bfv[0];
    __syncthreads();

    float sc = g_P[((size_t)tid*Bn + b)*96 + 88] + hdot;
    red[tid] = sc; __syncthreads();
    for (int o=128;o;o>>=1){ if (tid<o) red[tid]=fmaxf(red[tid],red[tid+o]); __syncthreads(); }
    float m = red[0]; __syncthreads();
    float e = expf(sc - m);
    red[tid] = e; __syncthreads();
    for (int o=128;o;o>>=1){ if (tid<o) red[tid]+=red[tid+o]; __syncthreads(); }
    float inv = 1.f/red[0];
    shw[tid] = e*inv;
    __syncthreads();

    if (tid < 176){
        int col = tid >> 1, hf = tid & 1;
        float acc = 0.f;
        const float* pb = g_P + (size_t)b*96 + col;
        int s0 = hf*128;
        #pragma unroll 4
        for (int s=s0; s<s0+128; s++) acc += shw[s]*pb[(size_t)s*((size_t)Bn*96)];
        pp[tid] = acc;
    }
    __syncthreads();
    if (tid < 88){
        float v = pp[2*tid] + pp[2*tid+1] + ((tid < An) ? b_a[tid] : b_t[tid-An]);
        shp[tid] = v;
        if (tid < An) out[(b*Tn + t)*An + tid] = v;
        else          out[Bn*Tn*An + (b*Tn + t)*NTn + (tid-An)] = v;
    }
    __syncthreads();
    if (tid == 0){
        int ia=0; float bv=shp[0];
        #pragma unroll
        for (int a=1;a<An;a++) if (shp[a]>bv){bv=shp[a]; ia=a;}
        int it=0; float tv=shp[An];
        for (int j=1;j<NTn;j++) if (shp[An+j]>tv){tv=shp[An+j]; it=j;}
        g_inp[b*2] = ia; g_inp[b*2+1] = it;
    }
    __syncthreads();
}

// persistent decoder: lstm + fused attention, 64 CTAs x 256 thr
__global__ __launch_bounds__(256,1) void dec_persist_k(
    const float* __restrict__ bias,
    const float* __restrict__ Wf, const float* __restrict__ bfv,
    const float* __restrict__ b_a, const float* __restrict__ b_t,
    float* __restrict__ out)
{
    extern __shared__ __align__(1024) uint32_t dsm[];
    __shared__ float shw[256], red[256], pp[256], shp[96];
    const int nIdx = blockIdx.x >> 2;
    const int m0   = (blockIdx.x & 3) * 64;
    float acc[2][4][4];
    for (int t=0;t<Tn;t++){
        int par = t & 1;
        gemm_tile<2>(dsm, g_h[par], nIdx, m0, acc);
        lstm_epi<2>(acc, bias, nullptr, nIdx, m0, t, par);
        gbar(256 + 2*t, 64);
        #pragma unroll 1
        for (int rb=0;rb<4;rb++)
            attn_row(blockIdx.x*4 + rb, t, par^1, Wf, bfv, b_a, b_t, out, shw, red, pp, shp);
        gbar(256 + 2*t + 1, 64);
    }
}

__global__ __launch_bounds__(256,1) void zx_k(){
    extern __shared__ __align__(1024) uint32_t dsm[];
    const int nIdx = blockIdx.x;
    const int m0   = blockIdx.y * 64;
    const int lane = threadIdx.x & 31, warp = threadIdx.x >> 5;
    const int wm = warp >> 2, wn = warp & 3;
    const int c4 = lane & 3, r4 = lane >> 2;
    float acc[2][4][4];
    gemm_tile<0>(dsm, g_emb_r, nIdx, m0, acc);
    #pragma unroll
    for (int i=0;i<2;i++)
    #pragma unroll
    for (int rh=0;rh<2;rh++){
        int gm = m0 + wm*32 + i*16 + rh*8 + r4;
        if (gm >= 1000) continue;
        #pragma unroll
        for (int j=0;j<4;j++)
        #pragma unroll
        for (int cc=0;cc<2;cc++){
            int col = nIdx*128 + wn*32 + j*8 + c4*2 + cc;
            g_zx[(size_t)gm*2048 + col] = acc[i][j][rh*2+cc];
        }
    }
}

__global__ __launch_bounds__(256,1) void proj_k(){
    extern __shared__ __align__(1024) uint32_t dsm[];
    const int m0 = blockIdx.y * 64;
    const int lane = threadIdx.x & 31, warp = threadIdx.x >> 5;
    const int wm = warp >> 2, wn = warp & 3;
    const int c4 = lane & 3, r4 = lane >> 2;
    float acc[2][4][4];
    gemm_tile<3>(dsm, g_enc_out, 0, m0, acc);
    #pragma unroll
    for (int i=0;i<2;i++)
    #pragma unroll
    for (int rh=0;rh<2;rh++){
        int gm = m0 + wm*32 + i*16 + rh*8 + r4;
        #pragma unroll
        for (int j=0;j<4;j++)
        #pragma unroll
        for (int cc=0;cc<2;cc++){
            int col = wn*32 + j*8 + c4*2 + cc;
            if (col < 96) g_P[(size_t)gm*96 + col] = acc[i][j][rh*2+cc];
        }
    }
}

extern "C" void kernel_launch(void* const* d_in, const int* in_sizes, int n_in,
                              void* d_out, int out_size)
{
    const int*   enc_input = (const int*)  d_in[0];
    const float* enc_embed = (const float*)d_in[2];
    const float* Wi_e      = (const float*)d_in[3];
    const float* Wh_e      = (const float*)d_in[4];
    const float* b_e       = (const float*)d_in[5];
    const float* act_emb   = (const float*)d_in[6];
    const float* tgt_emb   = (const float*)d_in[7];
    const float* Wi_d      = (const float*)d_in[8];
    const float* Wh_d      = (const float*)d_in[9];
    const float* b_d       = (const float*)d_in[10];
    const float* W_a       = (const float*)d_in[11];
    const float* b_a       = (const float*)d_in[12];
    const float* W_t       = (const float*)d_in[13];
    const float* b_t       = (const float*)d_in[14];
    const float* Wf        = (const float*)d_in[15];
    const float* bf        = (const float*)d_in[16];
    float* out = (float*)d_out;

    const int SMEM_SZ = 3*24576;
    cudaFuncSetAttribute(enc_persist_k, cudaFuncAttributeMaxDynamicSharedMemorySize, SMEM_SZ);
    cudaFuncSetAttribute(dec_persist_k, cudaFuncAttributeMaxDynamicSharedMemorySize, SMEM_SZ);
    cudaFuncSetAttribute(zx_k,          cudaFuncAttributeMaxDynamicSharedMemorySize, SMEM_SZ);
    cudaFuncSetAttribute(proj_k,        cudaFuncAttributeMaxDynamicSharedMemorySize, SMEM_SZ);

    init_k<<<(Bn*Hn + 255)/256, 256>>>();

    float* whe_r; cudaGetSymbolAddress((void**)&whe_r, g_whe_r);
    float* whd_r; cudaGetSymbolAddress((void**)&whd_r, g_whd_r);
    float* wie_r; cudaGetSymbolAddress((void**)&wie_r, g_wie_r);
    float* emb_r; cudaGetSymbolAddress((void**)&emb_r, g_emb_r);
    round_k<<<(4*Hn*Hn + 255)/256, 256>>>(Wh_e, whe_r, 4*Hn*Hn);
    round_k<<<(4*Hn*Hn + 255)/256, 256>>>(Wh_d, whd_r, 4*Hn*Hn);
    round_k<<<(4*Hn*En + 255)/256, 256>>>(Wi_e, wie_r, 4*Hn*En);
    round_k<<<(1000*En + 255)/256, 256>>>(enc_embed, emb_r, 1000*En);
    build_wpad_k<<<(128*Hn + 255)/256, 256>>>(W_a, W_t, Wf);
    build_dec_tables_k<<<(88*4*Hn + 255)/256, 256>>>(act_emb, tgt_emb, Wi_d);

    zx_k<<<dim3(16,16), 256, SMEM_SZ>>>();

    enc_persist_k<<<64, 256, SMEM_SZ>>>(b_e, enc_input);

    proj_k<<<dim3(1,1024), 256, SMEM_SZ>>>();

    dec_persist_k<<<64, 256, SMEM_SZ>>>(b_d, Wf, bf, b_a, b_t, out);
}

// round 9
// speedup vs baseline: 5.9803x; 1.6308x over previous
#include <cuda_runtime.h>
#include <math.h>
#include <stdint.h>

#define Bn 256
#define Sn 256
#define Tn 32
#define Hn 512
#define En 128
#define EDn 32
#define An 8
#define NTn 80

__device__ float g_h[2][Bn*Hn];
__device__ float g_c[Bn*Hn];
__device__ float g_enc_out[(size_t)Sn*Bn*Hn];
__device__ float g_zx[1000*4*Hn];
__device__ float g_act_z[An*4*Hn];
__device__ float g_tgt_z[NTn*4*Hn];
__device__ float g_P[(size_t)Sn*Bn*96];
__device__ float g_wpad[128*Hn];
__device__ float g_wie_r[4*Hn*En];
__device__ float g_whe_r[4*Hn*Hn];
__device__ float g_whd_r[4*Hn*Hn];
__device__ float g_emb_r[1000*En];
__device__ int   g_inp[Bn*2];
__device__ int   g_bar[384];

__device__ __forceinline__ float sigmoidf_(float x){ return 1.f/(1.f+expf(-x)); }
__device__ __forceinline__ float rna_f(float x){
    uint32_t u; asm("cvt.rna.tf32.f32 %0, %1;" : "=r"(u) : "f"(x));
    return __uint_as_float(u);
}
__device__ __forceinline__ uint32_t smem_u32(const void* p){
    uint32_t a;
    asm("{ .reg .u64 t; cvta.to.shared.u64 t, %1; cvt.u32.u64 %0, t; }" : "=r"(a) : "l"(p));
    return a;
}
#define CP_ASYNC16(dst, src) \
    asm volatile("cp.async.cg.shared.global [%0], [%1], 16;" :: "r"(dst), "l"(src))
#define CP_COMMIT() asm volatile("cp.async.commit_group;" ::: "memory")
#define CP_WAIT(n)  asm volatile("cp.async.wait_group %0;" :: "n"(n) : "memory")
#define MMA_TF32(d, a, b0v, b1v) \
    asm volatile("mma.sync.aligned.m16n8k8.row.col.f32.tf32.tf32.f32 " \
        "{%0,%1,%2,%3}, {%4,%5,%6,%7}, {%8,%9}, {%0,%1,%2,%3};" \
        : "+f"((d)[0]),"+f"((d)[1]),"+f"((d)[2]),"+f"((d)[3]) \
        : "r"((a)[0]),"r"((a)[1]),"r"((a)[2]),"r"((a)[3]), "r"(b0v),"r"(b1v))

__device__ __forceinline__ void gbar(int idx, int nc){
    __syncthreads();
    if (threadIdx.x == 0){
        int* p = &g_bar[idx];
        asm volatile("red.release.gpu.global.add.u32 [%0], 1;" :: "l"(p) : "memory");
        uint32_t v;
        do {
            asm volatile("ld.acquire.gpu.global.u32 %0, [%1];" : "=r"(v) : "l"(p) : "memory");
        } while (v < (uint32_t)nc);
    }
    __syncthreads();
}

__global__ void init_k(){
    int i = blockIdx.x*blockDim.x + threadIdx.x;
    if (i < Bn*Hn){ g_h[0][i]=0.f; g_h[1][i]=0.f; g_c[i]=0.f; }
    if (i < Bn*2) g_inp[i]=0;
    if (i < 384)  g_bar[i]=0;
}
__global__ void round_k(const float* __restrict__ s, float* __restrict__ d, int n){
    int i = blockIdx.x*blockDim.x + threadIdx.x;
    if (i < n) d[i] = rna_f(s[i]);
}
__global__ void build_wpad_k(const float* __restrict__ W_a, const float* __restrict__ W_t,
                             const float* __restrict__ Wf){
    int i = blockIdx.x*blockDim.x + threadIdx.x;
    if (i >= 128*Hn) return;
    int r = i >> 9, k = i & 511;
    float v = 0.f;
    if (r < 8)        v = W_a[r*Hn + k];
    else if (r < 88)  v = W_t[(r-8)*Hn + k];
    else if (r == 88) v = Wf[k];
    g_wpad[i] = rna_f(v);
}
__global__ void build_dec_tables_k(const float* __restrict__ act_emb,
                                   const float* __restrict__ tgt_emb,
                                   const float* __restrict__ Wi_d){
    int i = blockIdx.x*blockDim.x + threadIdx.x;
    if (i >= 88*4*Hn) return;
    int r = i >> 11, col = i & 2047;
    if (r < An){
        float a = 0.f; const float* w = Wi_d + col*64; const float* e = act_emb + r*EDn;
        #pragma unroll
        for (int k=0;k<EDn;k++) a += e[k]*w[k];
        g_act_z[r*4*Hn + col] = a;
    } else {
        r -= An;
        float a = 0.f; const float* w = Wi_d + col*64 + EDn; const float* e = tgt_emb + r*EDn;
        #pragma unroll
        for (int k=0;k<EDn;k++) a += e[k]*w[k];
        g_tgt_z[r*4*Hn + col] = a;
    }
}

// ---------------------------------------------------------------------------
// Old-style staged GEMM (kept for one-shot zx/proj kernels).
// MODE 0: zx = emb·Wi_e^T (K=128). MODE 3: P (K=512). 64x128 tile, 8 warps.
// ---------------------------------------------------------------------------
template<int MODE>
__device__ __forceinline__ void gemm_tile(uint32_t* dsm, const float* __restrict__ Ap,
                                          int nIdx, int m0, float (&acc)[2][4][4])
{
    constexpr int NC = (MODE==0) ? 4 : 16;
    const int tid = threadIdx.x;
    const int lane = tid & 31, warp = tid >> 5;
    const int wm = warp >> 2, wn = warp & 3;
    const int c4 = lane & 3, r4 = lane >> 2;

    #pragma unroll
    for (int i=0;i<2;i++)
        #pragma unroll
        for (int j=0;j<4;j++)
            #pragma unroll
            for (int q=0;q<4;q++) acc[i][j][q]=0.f;

    auto aRow = [&](int m)->const float* {
        if (MODE==0){ int rr=m0+m; if (rr>999) rr=999; return Ap + (size_t)rr*En; }
        return Ap + (size_t)(m0+m)*Hn;
    };
    auto bRow = [&](int rn)->const float* {
        if (MODE==0) return g_wie_r + (size_t)(nIdx*128 + rn)*En;
        return g_wpad + (size_t)rn*Hn;
    };
    const uint32_t smb = smem_u32(dsm);
    auto load_chunk = [&](int c, int st){
        uint32_t base = smb + (uint32_t)st*24576u;
        int k0 = c*32;
        #pragma unroll
        for (int i=0;i<2;i++){
            int u = tid + i*256;
            int m = u>>3, g = u&7;
            CP_ASYNC16(base + (uint32_t)(m*128 + ((g^(m&7))<<4)), aRow(m) + k0 + g*4);
        }
        #pragma unroll
        for (int i=0;i<4;i++){
            int u = tid + i*256;
            int rn = u>>3, g = u&7;
            CP_ASYNC16(base + 8192u + (uint32_t)(rn*128 + ((g^(rn&7))<<4)), bRow(rn) + k0 + g*4);
        }
        CP_COMMIT();
    };

    load_chunk(0,0);
    load_chunk(1,1);

    #pragma unroll 1
    for (int c=0;c<NC;c++){
        if (c+2 < NC) load_chunk(c+2, (c+2)%3);
        if (c+2 < NC) { CP_WAIT(2); } else if (c+1 < NC) { CP_WAIT(1); } else { CP_WAIT(0); }
        __syncthreads();
        const uint32_t* S = dsm + (c%3)*6144;
        #pragma unroll
        for (int ks=0;ks<4;ks++){
            int sw0 = (((2*ks  ) ^ r4) << 2) + c4;
            int sw1 = (((2*ks+1) ^ r4) << 2) + c4;
            uint32_t a[2][4];
            #pragma unroll
            for (int i=0;i<2;i++){
                int r0 = (wm*32 + i*16 + r4)*32;
                a[i][0]=S[r0+sw0]; a[i][1]=S[r0+256+sw0];
                a[i][2]=S[r0+sw1]; a[i][3]=S[r0+256+sw1];
            }
            #pragma unroll
            for (int j=0;j<4;j++){
                int nb = wn*32 + j*8;
                int n0 = 2048 + (nb + r4)*32;
                uint32_t b0 = S[n0+sw0], b1 = S[n0+sw1];
                MMA_TF32(acc[0][j], a[0], b0, b1);
                MMA_TF32(acc[1][j], a[1], b0, b1);
            }
        }
        __syncthreads();
    }
}

__global__ __launch_bounds__(256,1) void zx_k(){
    extern __shared__ __align__(1024) uint32_t dsm[];
    const int nIdx = blockIdx.x;
    const int m0   = blockIdx.y * 64;
    const int lane = threadIdx.x & 31, warp = threadIdx.x >> 5;
    const int wm = warp >> 2, wn = warp & 3;
    const int c4 = lane & 3, r4 = lane >> 2;
    float acc[2][4][4];
    gemm_tile<0>(dsm, g_emb_r, nIdx, m0, acc);
    #pragma unroll
    for (int i=0;i<2;i++)
    #pragma unroll
    for (int rh=0;rh<2;rh++){
        int gm = m0 + wm*32 + i*16 + rh*8 + r4;
        if (gm >= 1000) continue;
        #pragma unroll
        for (int j=0;j<4;j++)
        #pragma unroll
        for (int cc=0;cc<2;cc++){
            int col = nIdx*128 + wn*32 + j*8 + c4*2 + cc;
            g_zx[(size_t)gm*2048 + col] = acc[i][j][rh*2+cc];
        }
    }
}

__global__ __launch_bounds__(256,1) void proj_k(){
    extern __shared__ __align__(1024) uint32_t dsm[];
    const int m0 = blockIdx.y * 64;
    const int lane = threadIdx.x & 31, warp = threadIdx.x >> 5;
    const int wm = warp >> 2, wn = warp & 3;
    const int c4 = lane & 3, r4 = lane >> 2;
    float acc[2][4][4];
    gemm_tile<3>(dsm, g_enc_out, 0, m0, acc);
    #pragma unroll
    for (int i=0;i<2;i++)
    #pragma unroll
    for (int rh=0;rh<2;rh++){
        int gm = m0 + wm*32 + i*16 + rh*8 + r4;
        #pragma unroll
        for (int j=0;j<4;j++)
        #pragma unroll
        for (int cc=0;cc<2;cc++){
            int col = wn*32 + j*8 + c4*2 + cc;
            if (col < 96) g_P[(size_t)gm*96 + col] = acc[i][j][rh*2+cc];
        }
    }
}

// ---------------------------------------------------------------------------
// Persistent recurrent step kernel. 128 CTAs = 32 N-slices x 4 M-tiles.
// CTA tile: 64 rows x 64 cols (16 units x 4 gates). Weights (64x512) live
// in SMEM for the whole kernel; only A (h) is streamed per chunk (3-stage).
// smem: A 3 x 8KB = 24KB @u32[0..6144) ; B 16 chunks x 8KB = 128KB @u32[6144..)
// warp tile 16x32: wm=warp>>1 (rows), wn=warp&1 (8-unit half).
// ---------------------------------------------------------------------------
__device__ float attn_shw[1];   // (unused placeholder)

template<int MODE>  // 1 = encoder, 2 = decoder
__global__ __launch_bounds__(256,1) void step_persist_k(
    const float* __restrict__ bias, const int* __restrict__ enc_input,
    const float* __restrict__ Wf, const float* __restrict__ bfv,
    const float* __restrict__ b_a, const float* __restrict__ b_t,
    float* __restrict__ out)
{
    extern __shared__ __align__(1024) uint32_t dsm[];
    __shared__ float shw[256], red[256], pp[256], shp[96];
    const int tid = threadIdx.x;
    const int lane = tid & 31, wid = tid >> 5;
    const int wm = wid >> 1, wn = wid & 1;
    const int c4 = lane & 3, r4 = lane >> 2;
    const int nIdx = blockIdx.x >> 2;
    const int m0   = (blockIdx.x & 3) * 64;
    const uint32_t smb = smem_u32(dsm);
    const int NSTEP = (MODE==1) ? Sn : Tn;

    // ---- load persistent weight slice: rows rn = gate*16 + ul ----
    {
        const float* W = (MODE==1) ? g_whe_r : g_whd_r;
        #pragma unroll 1
        for (int ch=0; ch<16; ch++){
            #pragma unroll
            for (int i=0;i<2;i++){
                int u = tid + i*256;
                int rn = u>>3, g = u&7;
                int gate = rn>>4, ul = rn&15;
                const float* src = W + (size_t)(gate*Hn + nIdx*16 + ul)*Hn + ch*32 + g*4;
                CP_ASYNC16(smb + 24576u + (uint32_t)(ch*8192 + rn*128 + ((g^(rn&7))<<4)), src);
            }
        }
        CP_COMMIT();
    }

    auto loadA = [&](const float* hin, int c, int st){
        uint32_t base = smb + (uint32_t)st*8192u;
        int k0 = c*32;
        #pragma unroll
        for (int i=0;i<2;i++){
            int u = tid + i*256;
            int m = u>>3, g = u&7;
            CP_ASYNC16(base + (uint32_t)(m*128 + ((g^(m&7))<<4)),
                       hin + (size_t)(m0+m)*Hn + k0 + g*4);
        }
        CP_COMMIT();
    };

    float acc[4][4];

    #pragma unroll 1
    for (int t=0; t<NSTEP; t++){
        int par = t & 1;
        const float* hin = g_h[par];

        #pragma unroll
        for (int j=0;j<4;j++)
            #pragma unroll
            for (int q=0;q<4;q++) acc[j][q]=0.f;

        loadA(hin, 0, 0);
        loadA(hin, 1, 1);
        #pragma unroll 1
        for (int c=0;c<16;c++){
            if (c+2 < 16) loadA(hin, c+2, (c+2)%3);
            if (c+2 < 16) { CP_WAIT(2); } else if (c+1 < 16) { CP_WAIT(1); } else { CP_WAIT(0); }
            __syncthreads();
            const uint32_t* SA = dsm + (c%3)*2048;
            const uint32_t* SB = dsm + 6144 + c*2048;
            #pragma unroll
            for (int ks=0;ks<4;ks++){
                int sw0 = (((2*ks  ) ^ r4) << 2) + c4;
                int sw1 = (((2*ks+1) ^ r4) << 2) + c4;
                uint32_t a[4];
                int r0 = (wm*16 + r4)*32;
                a[0]=SA[r0+sw0]; a[1]=SA[r0+256+sw0];
                a[2]=SA[r0+sw1]; a[3]=SA[r0+256+sw1];
                #pragma unroll
                for (int j=0;j<4;j++){
                    int n0 = (j*16 + wn*8 + r4)*32;
                    uint32_t b0 = SB[n0+sw0], b1 = SB[n0+sw1];
                    MMA_TF32(acc[j], a, b0, b1);
                }
            }
            __syncthreads();
        }

        // ---- LSTM epilogue: all 4 gates in registers ----
        #pragma unroll
        for (int rh=0;rh<2;rh++){
            int bg = m0 + wm*16 + rh*8 + r4;
            const float *x0, *x1 = nullptr;
            if (MODE==1){ x0 = g_zx + (size_t)enc_input[bg*Sn + t]*2048; }
            else { x0 = g_act_z + (size_t)g_inp[bg*2]*2048;
                   x1 = g_tgt_z + (size_t)g_inp[bg*2+1]*2048; }
            float* hout = g_h[par^1] + (size_t)bg*Hn;
            float* crow = g_c + (size_t)bg*Hn;
            float* eout = g_enc_out + ((size_t)t*Bn + bg)*Hn;
            #pragma unroll
            for (int cc=0;cc<2;cc++){
                int u = nIdx*16 + wn*8 + c4*2 + cc;
                int q = rh*2 + cc;
                float xi, xf, xg, xo;
                if (MODE==1){ xi=x0[u]; xf=x0[512+u]; xg=x0[1024+u]; xo=x0[1536+u]; }
                else { xi=x0[u]+x1[u]; xf=x0[512+u]+x1[512+u];
                       xg=x0[1024+u]+x1[1024+u]; xo=x0[1536+u]+x1[1536+u]; }
                float zi = acc[0][q] + bias[       u] + xi;
                float zf = acc[1][q] + bias[ 512 + u] + xf;
                float zg = acc[2][q] + bias[1024 + u] + xg;
                float zo = acc[3][q] + bias[1536 + u] + xo;
                float co = crow[u];
                float cn = sigmoidf_(zf)*co + sigmoidf_(zi)*tanhf(zg);
                crow[u] = cn;
                float hn = rna_f(sigmoidf_(zo)*tanhf(cn));
                hout[u] = hn;
                if (MODE==1) eout[u] = hn;
            }
        }

        if (MODE==1){
            gbar(t, 128);
        } else {
            gbar(256 + 2*t, 128);
            // fused attention: 2 batch rows per CTA
            #pragma unroll 1
            for (int rb=0;rb<2;rb++){
                int b = blockIdx.x*2 + rb;
                const float* h = g_h[par^1] + (size_t)b*Hn;

                float part = h[tid]*Wf[512+tid] + h[tid+256]*Wf[768+tid];
                red[tid] = part; __syncthreads();
                for (int o=128;o;o>>=1){ if (tid<o) red[tid]+=red[tid+o]; __syncthreads(); }
                float hdot = red[0] + bfv[0];
                __syncthreads();

                float sc = g_P[((size_t)tid*Bn + b)*96 + 88] + hdot;
                red[tid] = sc; __syncthreads();
                for (int o=128;o;o>>=1){ if (tid<o) red[tid]=fmaxf(red[tid],red[tid+o]); __syncthreads(); }
                float m = red[0]; __syncthreads();
                float e = expf(sc - m);
                red[tid] = e; __syncthreads();
                for (int o=128;o;o>>=1){ if (tid<o) red[tid]+=red[tid+o]; __syncthreads(); }
                float inv = 1.f/red[0];
                shw[tid] = e*inv;
                __syncthreads();

                if (tid < 176){
                    int col = tid >> 1, hf = tid & 1;
                    float a2 = 0.f;
                    const float* pb = g_P + (size_t)b*96 + col;
                    int s0 = hf*128;
                    #pragma unroll 4
                    for (int s=s0; s<s0+128; s++) a2 += shw[s]*pb[(size_t)s*((size_t)Bn*96)];
                    pp[tid] = a2;
                }
                __syncthreads();
                if (tid < 88){
                    float v = pp[2*tid] + pp[2*tid+1] + ((tid < An) ? b_a[tid] : b_t[tid-An]);
                    shp[tid] = v;
                    if (tid < An) out[(b*Tn + t)*An + tid] = v;
                    else          out[Bn*Tn*An + (b*Tn + t)*NTn + (tid-An)] = v;
                }
                __syncthreads();
                if (tid == 0){
                    int ia=0; float bv=shp[0];
                    #pragma unroll
                    for (int a=1;a<An;a++) if (shp[a]>bv){bv=shp[a]; ia=a;}
                    int it=0; float tv=shp[An];
                    for (int j=1;j<NTn;j++) if (shp[An+j]>tv){tv=shp[An+j]; it=j;}
                    g_inp[b*2] = ia; g_inp[b*2+1] = it;
                }
                __syncthreads();
            }
            gbar(256 + 2*t + 1, 128);
        }
    }
}

extern "C" void kernel_launch(void* const* d_in, const int* in_sizes, int n_in,
                              void* d_out, int out_size)
{
    const int*   enc_input = (const int*)  d_in[0];
    const float* enc_embed = (const float*)d_in[2];
    const float* Wi_e      = (const float*)d_in[3];
    const float* Wh_e      = (const float*)d_in[4];
    const float* b_e       = (const float*)d_in[5];
    const float* act_emb   = (const float*)d_in[6];
    const float* tgt_emb   = (const float*)d_in[7];
    const float* Wi_d      = (const float*)d_in[8];
    const float* Wh_d      = (const float*)d_in[9];
    const float* b_d       = (const float*)d_in[10];
    const float* W_a       = (const float*)d_in[11];
    const float* b_a       = (const float*)d_in[12];
    const float* W_t       = (const float*)d_in[13];
    const float* b_t       = (const float*)d_in[14];
    const float* Wf        = (const float*)d_in[15];
    const float* bf        = (const float*)d_in[16];
    float* out = (float*)d_out;

    const int GEMM_SMEM = 3*24576;          // zx/proj
    const int STEP_SMEM = 24576 + 131072;   // A ring + persistent B
    cudaFuncSetAttribute(zx_k,   cudaFuncAttributeMaxDynamicSharedMemorySize, GEMM_SMEM);
    cudaFuncSetAttribute(proj_k, cudaFuncAttributeMaxDynamicSharedMemorySize, GEMM_SMEM);
    cudaFuncSetAttribute(step_persist_k<1>, cudaFuncAttributeMaxDynamicSharedMemorySize, STEP_SMEM);
    cudaFuncSetAttribute(step_persist_k<2>, cudaFuncAttributeMaxDynamicSharedMemorySize, STEP_SMEM);

    init_k<<<(Bn*Hn + 255)/256, 256>>>();

    float* whe_r; cudaGetSymbolAddress((void**)&whe_r, g_whe_r);
    float* whd_r; cudaGetSymbolAddress((void**)&whd_r, g_whd_r);
    float* wie_r; cudaGetSymbolAddress((void**)&wie_r, g_wie_r);
    float* emb_r; cudaGetSymbolAddress((void**)&emb_r, g_emb_r);
    round_k<<<(4*Hn*Hn + 255)/256, 256>>>(Wh_e, whe_r, 4*Hn*Hn);
    round_k<<<(4*Hn*Hn + 255)/256, 256>>>(Wh_d, whd_r, 4*Hn*Hn);
    round_k<<<(4*Hn*En + 255)/256, 256>>>(Wi_e, wie_r, 4*Hn*En);
    round_k<<<(1000*En + 255)/256, 256>>>(enc_embed, emb_r, 1000*En);
    build_wpad_k<<<(128*Hn + 255)/256, 256>>>(W_a, W_t, Wf);
    build_dec_tables_k<<<(88*4*Hn + 255)/256, 256>>>(act_emb, tgt_emb, Wi_d);

    zx_k<<<dim3(16,16), 256, GEMM_SMEM>>>();

    step_persist_k<1><<<128, 256, STEP_SMEM>>>(b_e, enc_input, nullptr, nullptr,
                                               nullptr, nullptr, nullptr);

    proj_k<<<dim3(1,1024), 256, GEMM_SMEM>>>();

    step_persist_k<2><<<128, 256, STEP_SMEM>>>(b_d, nullptr, Wf, bf, b_a, b_t, out);
}